// round 7
// baseline (speedup 1.0000x reference)
#include <cuda_runtime.h>
#include <cuda_bf16.h>
#include <cstdint>

#define NSYMS  256
#define NSTEPS 8192
#define NCH    62
#define HID    16

// ===========================================================================
// Pre-packed B fragments for mma.m16n8k16:
//   g_Bfrag[(ks*8+nt)*32 + lane] = { bh0, bh1, bl0, bl1 }
//   lane (g=lane/4, q=lane%4), n = nt*8+g, k0 = ks*16+2q:
//     b*0 = bf16x2( w(k0), w(k0+1) ), b*1 = bf16x2( w(k0+8), w(k0+9) )
//   w(k): k 0..61 -> market cin k+2; k=62 -> sym (cin 0); k=63 -> t (cin 1)
// ===========================================================================
__device__ uint4 g_Bfrag[4 * 8 * 32];

__global__ void build_weff(const float* __restrict__ W1h, const float* __restrict__ M1h,
                           const float* __restrict__ W2h, const float* __restrict__ M2h,
                           const float* __restrict__ W3h, const float* __restrict__ M3h) {
    __shared__ float W1[HID * 64];
    __shared__ float W2[HID * HID];
    __shared__ float W3[64 * HID];
    __shared__ float T2[HID * 64];
    __shared__ float Wt[64 * 64];   // [cin][o]
    const int tid = threadIdx.x;

    for (int i = tid; i < HID * 64; i += 256)
        W1[i] = tanhf(W1h[i]) * (1.0f / (1.0f + expf(-M1h[i])));
    for (int i = tid; i < HID * HID; i += 256)
        W2[i] = tanhf(W2h[i]) * (1.0f / (1.0f + expf(-M2h[i])));
    for (int i = tid; i < 64 * HID; i += 256)
        W3[i] = tanhf(W3h[i]) * (1.0f / (1.0f + expf(-M3h[i])));
    __syncthreads();

    for (int i = tid; i < HID * 64; i += 256) {
        int h = i >> 6, c = i & 63;
        float s = 0.0f;
#pragma unroll
        for (int k = 0; k < HID; k++) s += W2[h * HID + k] * W1[k * 64 + c];
        T2[i] = s;
    }
    __syncthreads();

    for (int i = tid; i < 64 * 64; i += 256) {
        int o = i >> 6, c = i & 63;
        float s = 0.0f;
#pragma unroll
        for (int k = 0; k < HID; k++) s += W3[o * HID + k] * T2[k * 64 + c];
        Wt[c * 64 + o] = s;
    }
    __syncthreads();

    for (int i = tid; i < 1024; i += 256) {
        int lane = i & 31, nt = (i >> 5) & 7, ks = i >> 8;
        int g = lane >> 2, q = lane & 3;
        int n = nt * 8 + g;
        int k0 = ks * 16 + 2 * q;

        float w[4];
#pragma unroll
        for (int j = 0; j < 4; j++) {
            int k = k0 + (j >> 1) * 8 + (j & 1);
            int cin = (k < 62) ? (k + 2) : (k - 62);
            w[j] = Wt[cin * 64 + n];
        }
        float wh[4], wl[4];
#pragma unroll
        for (int j = 0; j < 4; j++) {
            __nv_bfloat16 b = __float2bfloat16(w[j]);
            wh[j] = __bfloat162float(b);
            wl[j] = w[j] - wh[j];
        }
        __nv_bfloat162 h01 = __floats2bfloat162_rn(wh[0], wh[1]);
        __nv_bfloat162 h89 = __floats2bfloat162_rn(wh[2], wh[3]);
        __nv_bfloat162 l01 = __floats2bfloat162_rn(wl[0], wl[1]);
        __nv_bfloat162 l89 = __floats2bfloat162_rn(wl[2], wl[3]);
        uint4 u;
        u.x = *reinterpret_cast<uint32_t*>(&h01);
        u.y = *reinterpret_cast<uint32_t*>(&h89);
        u.z = *reinterpret_cast<uint32_t*>(&l01);
        u.w = *reinterpret_cast<uint32_t*>(&l89);
        g_Bfrag[i] = u;
    }
}

// ===========================================================================
// PTX helpers
// ===========================================================================
__device__ __forceinline__ void mma16816(float& d0, float& d1, float& d2, float& d3,
                                         uint32_t a0, uint32_t a1, uint32_t a2, uint32_t a3,
                                         uint32_t b0, uint32_t b1) {
    asm volatile("mma.sync.aligned.m16n8k16.row.col.f32.bf16.bf16.f32 "
                 "{%0,%1,%2,%3}, {%4,%5,%6,%7}, {%8,%9}, {%0,%1,%2,%3};"
                 : "+f"(d0), "+f"(d1), "+f"(d2), "+f"(d3)
                 : "r"(a0), "r"(a1), "r"(a2), "r"(a3), "r"(b0), "r"(b1));
}

__device__ __forceinline__ void cvt_split(float x, float y, uint32_t& h, uint32_t& l) {
    asm("cvt.rn.bf16x2.f32 %0, %1, %2;" : "=r"(h) : "f"(y), "f"(x));  // lo=x, hi=y
    uint32_t hxb = h << 16;
    uint32_t hyb = h & 0xFFFF0000u;
    float lx = x - __uint_as_float(hxb);
    float ly = y - __uint_as_float(hyb);
    asm("cvt.rn.bf16x2.f32 %0, %1, %2;" : "=r"(l) : "f"(ly), "f"(lx));
}

__device__ __forceinline__ uint32_t smem_u32(const void* p) {
    uint32_t a;
    asm("{ .reg .u64 t; cvta.to.shared.u64 t, %1; cvt.u32.u64 %0, t; }" : "=r"(a) : "l"(p));
    return a;
}
#define STS64F(a, f0, f1) \
    asm volatile("st.shared.v2.f32 [%0], {%1, %2};" :: "r"(a), "f"(f0), "f"(f1) : "memory")
#define LDS128F(f0, f1, f2, f3, a) \
    asm volatile("ld.shared.v4.f32 {%0, %1, %2, %3}, [%4];" : "=f"(f0), "=f"(f1), "=f"(f2), "=f"(f3) : "r"(a))
#define STG128CS(p, f0, f1, f2, f3) \
    asm volatile("st.global.cs.v4.f32 [%0], {%1, %2, %3, %4};" :: "l"(p), "f"(f0), "f"(f1), "f"(f2), "f"(f3) : "memory")
#define PREFETCH_L2(p) \
    asm volatile("prefetch.global.L2 [%0];" :: "l"(p))

// ===========================================================================
// Main kernel: register-resident split-bf16 tensor GEMM.
//   CTA: 256 threads = 8 warps; warp = 16 rows x 64 outs; ITERS=4 -> 512 rows.
//   L2 prefetch of next slab (zero register cost); epilogue via per-warp
//   XOR-swizzled smem tile -> coalesced streaming STG.128.
// ===========================================================================
#define ITERS 4

__global__ void __launch_bounds__(256, 1)
encode_kernel(const float* __restrict__ market, float* __restrict__ out) {
    __shared__ float sepi[8 * 16 * 64];   // 32KB: per-warp 16x64 D tile (swizzled)

    const int tid  = threadIdx.x;
    const int warp = tid >> 5;
    const int lane = tid & 31;
    const int g = lane >> 2;     // 0..7
    const int q = lane & 3;      // 0..3

    // ---- B fragments: 128 regs, loaded once
    uint32_t BH0[32], BH1[32], BL0[32], BL1[32];
#pragma unroll
    for (int i = 0; i < 32; i++) {
        uint4 u = g_Bfrag[i * 32 + lane];
        BH0[i] = u.x; BH1[i] = u.y; BL0[i] = u.z; BL1[i] = u.w;
    }

    const long long cta_row0 = (long long)blockIdx.x * (128 * ITERS);
    const float sval = (float)(cta_row0 >> 13);
    const int   tcta = (int)(cta_row0 & (NSTEPS - 1));

    const uint32_t wb = smem_u32(sepi) + warp * 4096;   // per-warp 4KB tile

    // Prefetch iter-0 slab into L2 (fires early; harness graph replays keep L2 warm anyway)
    {
        const char* slab = (const char*)(market + cta_row0 * NCH);
        if (tid < 248) PREFETCH_L2(slab + tid * 128);
    }

#pragma unroll 1
    for (int it = 0; it < ITERS; it++) {
        // ---- L2 prefetch of next iter's 128-row slab (31744B = 248 lines)
        if (it + 1 < ITERS) {
            const char* slab = (const char*)(market + (cta_row0 + (long long)(it + 1) * 128) * NCH);
            if (tid < 248) PREFETCH_L2(slab + tid * 128);
        }

        // ---- load this iter's fragments (16 x LDG.64)
        const int rloc = it * 128 + warp * 16 + g;
        const float* p0 = market + (cta_row0 + rloc) * NCH;
        const float* p1 = p0 + 8 * NCH;

        float2 vc[16];   // [ks*4 + {p0 pair0, p0 pair1, p1 pair0, p1 pair1}]
#pragma unroll
        for (int ks = 0; ks < 4; ks++) {
            const int c0 = ks * 16 + 2 * q;
            vc[ks * 4 + 0] = *(const float2*)(p0 + c0);
            vc[ks * 4 + 2] = *(const float2*)(p1 + c0);
            if (ks == 3 && q == 3) {
                float tg = (float)(tcta + rloc);
                vc[13] = make_float2(sval, tg);
                vc[15] = make_float2(sval, tg + 8.0f);
            } else {
                vc[ks * 4 + 1] = *(const float2*)(p0 + c0 + 8);
                vc[ks * 4 + 3] = *(const float2*)(p1 + c0 + 8);
            }
        }

        // ---- convert + MMA
        float acc[32];
#pragma unroll
        for (int i = 0; i < 32; i++) acc[i] = 0.0f;

#pragma unroll
        for (int ks = 0; ks < 4; ks++) {
            uint32_t ah0, ah1, ah2, ah3, al0, al1, al2, al3;
            cvt_split(vc[ks*4+0].x, vc[ks*4+0].y, ah0, al0);   // row g,   pair0
            cvt_split(vc[ks*4+2].x, vc[ks*4+2].y, ah1, al1);   // row g+8, pair0
            cvt_split(vc[ks*4+1].x, vc[ks*4+1].y, ah2, al2);   // row g,   pair1
            cvt_split(vc[ks*4+3].x, vc[ks*4+3].y, ah3, al3);   // row g+8, pair1
#pragma unroll
            for (int nt = 0; nt < 8; nt++) {
                const int bi = ks * 8 + nt;
                mma16816(acc[nt*4+0], acc[nt*4+1], acc[nt*4+2], acc[nt*4+3],
                         ah0, ah1, ah2, ah3, BH0[bi], BH1[bi]);
                mma16816(acc[nt*4+0], acc[nt*4+1], acc[nt*4+2], acc[nt*4+3],
                         ah0, ah1, ah2, ah3, BL0[bi], BL1[bi]);
                mma16816(acc[nt*4+0], acc[nt*4+1], acc[nt*4+2], acc[nt*4+3],
                         al0, al1, al2, al3, BH0[bi], BH1[bi]);
            }
        }

        // ---- epilogue: fragments -> swizzled smem -> coalesced streaming STG.128
        // smem tile: 16 rows x 64 floats; float4-granule XOR swizzle: phys_f4 = logical_f4 ^ row
        {
            const int qhi = q >> 1, qlo = q & 1;
#pragma unroll
            for (int nt = 0; nt < 8; nt++) {
                uint32_t f4a = (uint32_t)((2 * nt + qhi) ^ g);
                uint32_t f4b = (uint32_t)((2 * nt + qhi) ^ (g + 8));
                STS64F(wb + g * 256 + f4a * 16 + qlo * 8,       acc[nt*4+0], acc[nt*4+1]);
                STS64F(wb + (g + 8) * 256 + f4b * 16 + qlo * 8, acc[nt*4+2], acc[nt*4+3]);
            }
        }
        __syncwarp();

        {
            float* obase = out + (cta_row0 + (long long)it * 128 + warp * 16) * 64;
#pragma unroll
            for (int i = 0; i < 8; i++) {
                int slot = i * 32 + lane;
                int row = slot >> 4;
                int c4 = slot & 15;
                uint32_t f4 = (uint32_t)(c4 ^ row);
                float f0, f1, f2, f3;
                LDS128F(f0, f1, f2, f3, wb + row * 256 + f4 * 16);
                STG128CS(obase + row * 64 + c4 * 4, f0, f1, f2, f3);
            }
        }
        __syncwarp();
    }
}

// ---------------------------------------------------------------------------
extern "C" void kernel_launch(void* const* d_in, const int* in_sizes, int n_in,
                              void* d_out, int out_size) {
    const float* market = (const float*)d_in[0];
    build_weff<<<1, 256>>>((const float*)d_in[1], (const float*)d_in[2],
                           (const float*)d_in[3], (const float*)d_in[4],
                           (const float*)d_in[5], (const float*)d_in[6]);

    const int nblocks = (NSYMS * NSTEPS) / (128 * ITERS);   // 4096
    encode_kernel<<<nblocks, 256>>>(market, (float*)d_out);
}

// round 9
// speedup vs baseline: 1.1192x; 1.1192x over previous
#include <cuda_runtime.h>
#include <cuda_fp16.h>
#include <cuda_bf16.h>
#include <cstdint>

#define NSYMS  256
#define NSTEPS 8192
#define NCH    62
#define HID    16

// ===========================================================================
// Pre-packed fp16 B fragments for mma.m16n8k16 (hi term only):
//   g_Bfrag16[(ks*8+nt)*32 + lane] = { h01, h89 }
//   lane (g=lane/4, q=lane%4), n = nt*8+g, k0 = ks*16+2q:
//     h01 = f16x2( w(k0), w(k0+1) ), h89 = f16x2( w(k0+8), w(k0+9) )
//   w(k): k 0..61 -> market cin k+2; k = 62,63 -> ZERO (sym/t handled in fp32)
// g_Wst[0..63]  = W_eff[o][cin=0] (sym weights, fp32)
// g_Wst[64..127]= W_eff[o][cin=1] (t weights, fp32)
// ===========================================================================
__device__ uint2 g_Bfrag16[4 * 8 * 32];
__device__ float g_Wst[128];

__global__ void build_weff(const float* __restrict__ W1h, const float* __restrict__ M1h,
                           const float* __restrict__ W2h, const float* __restrict__ M2h,
                           const float* __restrict__ W3h, const float* __restrict__ M3h) {
    __shared__ float W1[HID * 64];
    __shared__ float W2[HID * HID];
    __shared__ float W3[64 * HID];
    __shared__ float T2[HID * 64];
    __shared__ float Wt[64 * 64];   // [cin][o]
    const int tid = threadIdx.x;

    for (int i = tid; i < HID * 64; i += 256)
        W1[i] = tanhf(W1h[i]) * (1.0f / (1.0f + expf(-M1h[i])));
    for (int i = tid; i < HID * HID; i += 256)
        W2[i] = tanhf(W2h[i]) * (1.0f / (1.0f + expf(-M2h[i])));
    for (int i = tid; i < 64 * HID; i += 256)
        W3[i] = tanhf(W3h[i]) * (1.0f / (1.0f + expf(-M3h[i])));
    __syncthreads();

    for (int i = tid; i < HID * 64; i += 256) {
        int h = i >> 6, c = i & 63;
        float s = 0.0f;
#pragma unroll
        for (int k = 0; k < HID; k++) s += W2[h * HID + k] * W1[k * 64 + c];
        T2[i] = s;
    }
    __syncthreads();

    for (int i = tid; i < 64 * 64; i += 256) {
        int o = i >> 6, c = i & 63;
        float s = 0.0f;
#pragma unroll
        for (int k = 0; k < HID; k++) s += W3[o * HID + k] * T2[k * 64 + c];
        Wt[c * 64 + o] = s;
    }
    __syncthreads();

    // fp16 B fragments (market columns only; k=62,63 zeroed)
    for (int i = tid; i < 1024; i += 256) {
        int lane = i & 31, nt = (i >> 5) & 7, ks = i >> 8;
        int g = lane >> 2, q = lane & 3;
        int n = nt * 8 + g;
        int k0 = ks * 16 + 2 * q;

        float w[4];
#pragma unroll
        for (int j = 0; j < 4; j++) {
            int k = k0 + (j >> 1) * 8 + (j & 1);
            w[j] = (k < 62) ? Wt[(k + 2) * 64 + n] : 0.0f;
        }
        __half2 h01 = __floats2half2_rn(w[0], w[1]);
        __half2 h89 = __floats2half2_rn(w[2], w[3]);
        uint2 u;
        u.x = *reinterpret_cast<uint32_t*>(&h01);
        u.y = *reinterpret_cast<uint32_t*>(&h89);
        g_Bfrag16[i] = u;
    }
    // sym / t fp32 weight rows
    for (int i = tid; i < 128; i += 256)
        g_Wst[i] = Wt[i];   // Wt[0..63] = cin0 (sym), Wt[64..127] = cin1 (t)
}

// ===========================================================================
// PTX helpers
// ===========================================================================
__device__ __forceinline__ void mma16816h(float& d0, float& d1, float& d2, float& d3,
                                          uint32_t a0, uint32_t a1, uint32_t a2, uint32_t a3,
                                          uint32_t b0, uint32_t b1) {
    asm volatile("mma.sync.aligned.m16n8k16.row.col.f32.f16.f16.f32 "
                 "{%0,%1,%2,%3}, {%4,%5,%6,%7}, {%8,%9}, {%0,%1,%2,%3};"
                 : "+f"(d0), "+f"(d1), "+f"(d2), "+f"(d3)
                 : "r"(a0), "r"(a1), "r"(a2), "r"(a3), "r"(b0), "r"(b1));
}

// split two fp32 into f16x2 hi (rn) + f16x2 lo residual (rn); lo half = x
__device__ __forceinline__ void cvt_split_h(float x, float y, uint32_t& h, uint32_t& l) {
    __half2 h2 = __floats2half2_rn(x, y);
    float2 hf = __half22float2(h2);
    __half2 l2 = __floats2half2_rn(x - hf.x, y - hf.y);
    h = *reinterpret_cast<uint32_t*>(&h2);
    l = *reinterpret_cast<uint32_t*>(&l2);
}

__device__ __forceinline__ uint32_t smem_u32(const void* p) {
    uint32_t a;
    asm("{ .reg .u64 t; cvta.to.shared.u64 t, %1; cvt.u32.u64 %0, t; }" : "=r"(a) : "l"(p));
    return a;
}
#define STS64F(a, f0, f1) \
    asm volatile("st.shared.v2.f32 [%0], {%1, %2};" :: "r"(a), "f"(f0), "f"(f1) : "memory")
#define LDS128F(f0, f1, f2, f3, a) \
    asm volatile("ld.shared.v4.f32 {%0, %1, %2, %3}, [%4];" : "=f"(f0), "=f"(f1), "=f"(f2), "=f"(f3) : "r"(a))

// ===========================================================================
// Main kernel: fp16 2-term tensor GEMM (market) + exact fp32 affine (sym, t).
//   CTA: 256 threads = 8 warps; warp = 16 rows x 64 outs; ITERS=4 -> 512 rows.
//   Register prefetch of next iter's fragments; per-warp swizzled epilogue.
// ===========================================================================
#define ITERS 4

__global__ void __launch_bounds__(256, 1)
encode_kernel(const float* __restrict__ market, float* __restrict__ out) {
    __shared__ float sepi[8 * 16 * 64];   // 32KB: per-warp 16x64 D tile (swizzled)
    __shared__ float scorr[128];          // [0..63] s*Wsym[o], [64..127] Wt[o]

    const int tid  = threadIdx.x;
    const int warp = tid >> 5;
    const int lane = tid & 31;
    const int g = lane >> 2;     // 0..7
    const int q = lane & 3;      // 0..3

    // ---- B fragments (hi only): 64 regs
    uint32_t BH0[32], BH1[32];
#pragma unroll
    for (int i = 0; i < 32; i++) {
        uint2 u = g_Bfrag16[i * 32 + lane];
        BH0[i] = u.x; BH1[i] = u.y;
    }

    const long long cta_row0 = (long long)blockIdx.x * (128 * ITERS);
    const float sval = (float)(cta_row0 >> 13);
    const int   tcta = (int)(cta_row0 & (NSTEPS - 1));

    if (tid < 64) {
        scorr[tid]      = sval * g_Wst[tid];
        scorr[64 + tid] = g_Wst[64 + tid];
    }
    __syncthreads();

    const uint32_t wb = smem_u32(sepi) + warp * 4096;   // per-warp 4KB tile

    // v layout per iter: [ks*4 + {p0 pair0, p0 pair1, p1 pair0, p1 pair1}]
    float2 vc[16], vn[16];

    // ---- preload iter 0
    {
        const int rloc = warp * 16 + g;
        const float* p0 = market + (cta_row0 + rloc) * NCH;
        const float* p1 = p0 + 8 * NCH;
#pragma unroll
        for (int ks = 0; ks < 4; ks++) {
            const int c0 = ks * 16 + 2 * q;
            vc[ks * 4 + 0] = *(const float2*)(p0 + c0);
            vc[ks * 4 + 2] = *(const float2*)(p1 + c0);
            if (ks == 3 && q == 3) {
                vc[13] = make_float2(0.0f, 0.0f);   // cols 62,63 handled in epilogue
                vc[15] = make_float2(0.0f, 0.0f);
            } else {
                vc[ks * 4 + 1] = *(const float2*)(p0 + c0 + 8);
                vc[ks * 4 + 3] = *(const float2*)(p1 + c0 + 8);
            }
        }
    }

#pragma unroll 1
    for (int it = 0; it < ITERS; it++) {
        // ---- register prefetch next iter (overlaps MMAs below)
        if (it + 1 < ITERS) {
            const int rloc = (it + 1) * 128 + warp * 16 + g;
            const float* p0 = market + (cta_row0 + rloc) * NCH;
            const float* p1 = p0 + 8 * NCH;
#pragma unroll
            for (int ks = 0; ks < 4; ks++) {
                const int c0 = ks * 16 + 2 * q;
                vn[ks * 4 + 0] = *(const float2*)(p0 + c0);
                vn[ks * 4 + 2] = *(const float2*)(p1 + c0);
                if (ks == 3 && q == 3) {
                    vn[13] = make_float2(0.0f, 0.0f);
                    vn[15] = make_float2(0.0f, 0.0f);
                } else {
                    vn[ks * 4 + 1] = *(const float2*)(p0 + c0 + 8);
                    vn[ks * 4 + 3] = *(const float2*)(p1 + c0 + 8);
                }
            }
        }

        // ---- convert + MMA: D = (Ah + Al) * Bh, fp32 accum
        float acc[32];
#pragma unroll
        for (int i = 0; i < 32; i++) acc[i] = 0.0f;

#pragma unroll
        for (int ks = 0; ks < 4; ks++) {
            uint32_t ah0, ah1, ah2, ah3, al0, al1, al2, al3;
            cvt_split_h(vc[ks*4+0].x, vc[ks*4+0].y, ah0, al0);   // row g,   pair0
            cvt_split_h(vc[ks*4+2].x, vc[ks*4+2].y, ah1, al1);   // row g+8, pair0
            cvt_split_h(vc[ks*4+1].x, vc[ks*4+1].y, ah2, al2);   // row g,   pair1
            cvt_split_h(vc[ks*4+3].x, vc[ks*4+3].y, ah3, al3);   // row g+8, pair1
#pragma unroll
            for (int nt = 0; nt < 8; nt++) {
                const int bi = ks * 8 + nt;
                mma16816h(acc[nt*4+0], acc[nt*4+1], acc[nt*4+2], acc[nt*4+3],
                          ah0, ah1, ah2, ah3, BH0[bi], BH1[bi]);
                mma16816h(acc[nt*4+0], acc[nt*4+1], acc[nt*4+2], acc[nt*4+3],
                          al0, al1, al2, al3, BH0[bi], BH1[bi]);
            }
        }

        // ---- epilogue: fragments -> swizzled smem -> +affine(s,t) -> coalesced STG
        {
            const int qhi = q >> 1, qlo = q & 1;
#pragma unroll
            for (int nt = 0; nt < 8; nt++) {
                uint32_t f4a = (uint32_t)((2 * nt + qhi) ^ g);
                uint32_t f4b = (uint32_t)((2 * nt + qhi) ^ (g + 8));
                STS64F(wb + g * 256 + f4a * 16 + qlo * 8,       acc[nt*4+0], acc[nt*4+1]);
                STS64F(wb + (g + 8) * 256 + f4b * 16 + qlo * 8, acc[nt*4+2], acc[nt*4+3]);
            }
        }
        __syncwarp();

        {
            float* obase = out + (cta_row0 + (long long)it * 128 + warp * 16) * 64;
            const float tbase = (float)(tcta + it * 128 + warp * 16);
#pragma unroll
            for (int i = 0; i < 8; i++) {
                int slot = i * 32 + lane;
                int row = slot >> 4;
                int c4 = slot & 15;
                uint32_t f4 = (uint32_t)(c4 ^ row);
                float f0, f1, f2, f3;
                LDS128F(f0, f1, f2, f3, wb + row * 256 + f4 * 16);
                float4 cr = *(const float4*)(scorr + c4 * 4);
                float4 wt = *(const float4*)(scorr + 64 + c4 * 4);
                float tv = tbase + (float)row;
                f0 += cr.x + tv * wt.x;
                f1 += cr.y + tv * wt.y;
                f2 += cr.z + tv * wt.z;
                f3 += cr.w + tv * wt.w;
                *(float4*)(obase + row * 64 + c4 * 4) = make_float4(f0, f1, f2, f3);
            }
        }
        __syncwarp();

        // rotate prefetch buffer
#pragma unroll
        for (int i = 0; i < 16; i++) vc[i] = vn[i];
    }
}

// ---------------------------------------------------------------------------
extern "C" void kernel_launch(void* const* d_in, const int* in_sizes, int n_in,
                              void* d_out, int out_size) {
    const float* market = (const float*)d_in[0];
    build_weff<<<1, 256>>>((const float*)d_in[1], (const float*)d_in[2],
                           (const float*)d_in[3], (const float*)d_in[4],
                           (const float*)d_in[5], (const float*)d_in[6]);

    const int nblocks = (NSYMS * NSTEPS) / (128 * ITERS);   // 4096
    encode_kernel<<<nblocks, 256>>>(market, (float*)d_out);
}